// round 5
// baseline (speedup 1.0000x reference)
#include <cuda_runtime.h>
#include <cuda_bf16.h>
#include <cstdint>
#include <math.h>

// NT-Xent loss, symmetric HMMA edition.
// sim = 2*(z z^T) is symmetric: only upper-triangle 128x128 tiles (it<=jt) are
// computed. Each off-diag tile contributes exp-sums to rows of BOTH blocks
// (row sums + in-register column sums). Per-tile sums go to G[it][jt][r]
// (every entry written exactly once), reduced by a second kernel.
// loss_i = -sim[i,i^8192] + 2 + log(sum_{j!=i} exp(sim_ij - 2)); out = mean.

#define N2 16384
#define DIM 128
#define NPAIRS 8256               // 128*129/2
#define GRID_MAIN 152
#define ROWB 272                  // padded SMEM row bytes (128 bf16 + 8 pad)
#define A0_OFF 0
#define A1_OFF 34816
#define B0_OFF 69632
#define B1_OFF 104448
#define RBUF_OFF 139264           // 4*128 floats = 2048 B
#define CBUF_OFF 141312           // 2*128 floats = 1024 B
#define SMEM_BYTES 142336

__device__ __nv_bfloat16 g_zbf[N2 * DIM];          // 4 MB
__device__ float g_G[128 * 128 * 128];              // 8 MB: G[it][jt][r]
__device__ float g_pos[N2];
__device__ float g_partials[128];

__device__ __forceinline__ uint32_t smem_u32(const void* p) {
    uint32_t a;
    asm("{ .reg .u64 t; cvta.to.shared.u64 t, %1; cvt.u32.u64 %0, t; }" : "=r"(a) : "l"(p));
    return a;
}
__device__ __forceinline__ void cp16(uint32_t dst, const void* src) {
    asm volatile("cp.async.cg.shared.global [%0], [%1], 16;" :: "r"(dst), "l"(src));
}
__device__ __forceinline__ void ldm_x4(uint32_t (&r)[4], uint32_t addr) {
    asm volatile("ldmatrix.sync.aligned.m8n8.x4.shared.b16 {%0,%1,%2,%3}, [%4];"
                 : "=r"(r[0]), "=r"(r[1]), "=r"(r[2]), "=r"(r[3]) : "r"(addr));
}
__device__ __forceinline__ void mma16816(float (&c)[4], const uint32_t (&a)[4],
                                         uint32_t b0, uint32_t b1) {
    asm volatile("mma.sync.aligned.m16n8k16.row.col.f32.bf16.bf16.f32 "
                 "{%0,%1,%2,%3},{%4,%5,%6,%7},{%8,%9},{%0,%1,%2,%3};"
                 : "+f"(c[0]), "+f"(c[1]), "+f"(c[2]), "+f"(c[3])
                 : "r"(a[0]), "r"(a[1]), "r"(a[2]), "r"(a[3]), "r"(b0), "r"(b1));
}
__device__ __forceinline__ float ex2(float x) {
    float y; asm("ex2.approx.f32 %0, %1;" : "=f"(y) : "f"(x)); return y;
}

// S(t) = number of pairs before row t in upper-triangle enumeration
__device__ __forceinline__ int Sfun(int t) { return t * 128 - (t * (t - 1)) / 2; }
__device__ __forceinline__ void decode_pair(int p, int& it, int& jt) {
    int t = (int)((257.0 - sqrt((double)(66049 - 8 * p))) * 0.5);
    if (t < 0) t = 0;
    if (t > 127) t = 127;
    while (t < 127 && Sfun(t + 1) <= p) t++;
    while (t > 0 && Sfun(t) > p) t--;
    it = t;
    jt = t + (p - Sfun(t));
}

__global__ void __launch_bounds__(256) convert_kernel(const float* __restrict__ z) {
    int i = blockIdx.x * blockDim.x + threadIdx.x;
    const float4 v = ((const float4*)z)[i];
    __nv_bfloat162 lo = __floats2bfloat162_rn(v.x, v.y);
    __nv_bfloat162 hi = __floats2bfloat162_rn(v.z, v.w);
    uint2 o;
    o.x = *(const uint32_t*)&lo;
    o.y = *(const uint32_t*)&hi;
    ((uint2*)g_zbf)[i] = o;
}

__device__ __forceinline__ void prefetch_tile(uint32_t smbase, const char* gsrc, int tid) {
    #pragma unroll
    for (int i = 0; i < 8; i++) {
        int c = tid + i * 256;
        int r = c >> 4, kc = c & 15;
        cp16(smbase + r * ROWB + kc * 16, gsrc + r * 256 + kc * 16);
    }
}
__device__ __forceinline__ void prefetch_pair(uint32_t s, int buf, int it, int jt, int tid) {
    const char* zbf = (const char*)g_zbf;
    prefetch_tile(s + (buf ? A1_OFF : A0_OFF), zbf + (size_t)it * 32768, tid);
    prefetch_tile(s + (buf ? B1_OFF : B0_OFF), zbf + (size_t)jt * 32768, tid);
}

__global__ void __launch_bounds__(256, 1) ntxent_sym_kernel() {
    extern __shared__ char sm[];
    const uint32_t s = smem_u32(sm);
    float* Rbuf = (float*)(sm + RBUF_OFF);    // [4 wn][128 rows]
    float* Cbuf = (float*)(sm + CBUF_OFF);    // [2 wm][128 cols]

    const int tid = threadIdx.x;
    const int w = tid >> 5, l = tid & 31;
    const int wm = w >> 2, wn = w & 3;
    const int stride = gridDim.x;

    const uint32_t laneA = (uint32_t)((l & 15) * ROWB + (l >> 4) * 16);
    const uint32_t laneB = (uint32_t)(((l & 7) + ((l >> 4) << 3)) * ROWB + (((l >> 3) & 1) << 4));
    const float C1 = 2.885390081777927f;      // 2*log2(e)

    int n0 = blockIdx.x;
    if (n0 < NPAIRS) {
        int it0, jt0;
        decode_pair(n0, it0, jt0);
        prefetch_pair(s, 0, it0, jt0, tid);
    }
    asm volatile("cp.async.commit_group;" ::: "memory");

    int ni = 0;
    for (int n = n0; n < NPAIRS; n += stride, ni++) {
        int it, jt;
        decode_pair(n, it, jt);
        const bool isDiag = (it == jt);
        const bool isPos = (jt - it == 64);

        __syncthreads();                       // prior reads of alt buffers + Rbuf done
        int nn = n + stride;
        if (nn < NPAIRS) {
            int it2, jt2;
            decode_pair(nn, it2, jt2);
            prefetch_pair(s, (ni + 1) & 1, it2, jt2, tid);
        }
        asm volatile("cp.async.commit_group;" ::: "memory");
        asm volatile("cp.async.wait_group 1;" ::: "memory");
        __syncthreads();                       // current pair visible

        const uint32_t Abase = s + ((ni & 1) ? A1_OFF : A0_OFF);
        const uint32_t Bbase = s + ((ni & 1) ? B1_OFF : B0_OFF);
        const uint32_t A_warp = Abase + (uint32_t)wm * 64 * ROWB + laneA;
        const uint32_t B_warp = Bbase + (uint32_t)wn * 32 * ROWB + laneB;

        float acc[4][4][4];
        #pragma unroll
        for (int mf = 0; mf < 4; mf++)
            #pragma unroll
            for (int nf = 0; nf < 4; nf++)
                #pragma unroll
                for (int q = 0; q < 4; q++) acc[mf][nf][q] = 0.f;

        #pragma unroll
        for (int ks = 0; ks < 8; ks++) {
            uint32_t a[4][4], b[2][4];
            #pragma unroll
            for (int mf = 0; mf < 4; mf++)
                ldm_x4(a[mf], A_warp + mf * (16 * ROWB) + ks * 32);
            #pragma unroll
            for (int nh = 0; nh < 2; nh++)
                ldm_x4(b[nh], B_warp + nh * (16 * ROWB) + ks * 32);
            #pragma unroll
            for (int mf = 0; mf < 4; mf++)
                #pragma unroll
                for (int nf = 0; nf < 4; nf++)
                    mma16816(acc[mf][nf], a[mf], b[nf >> 1][(nf & 1) * 2],
                             b[nf >> 1][(nf & 1) * 2 + 1]);
        }

        // ---- epilogue: rs (row sums) + cs (col sums) ----
        float rs[8], cs[8];
        #pragma unroll
        for (int u = 0; u < 8; u++) { rs[u] = 0.f; cs[u] = 0.f; }

        if (!isDiag && !isPos) {
            #pragma unroll
            for (int mf = 0; mf < 4; mf++)
                #pragma unroll
                for (int nf = 0; nf < 4; nf++)
                    #pragma unroll
                    for (int q = 0; q < 4; q++) {
                        float e = ex2(fmaf(acc[mf][nf][q], C1, -C1));
                        rs[mf * 2 + (q >> 1)] += e;
                        cs[nf * 2 + (q & 1)] += e;
                    }
        } else if (isDiag) {
            #pragma unroll
            for (int mf = 0; mf < 4; mf++)
                #pragma unroll
                for (int nf = 0; nf < 4; nf++)
                    #pragma unroll
                    for (int q = 0; q < 4; q++) {
                        int r = wm * 64 + mf * 16 + (l >> 2) + (q >> 1) * 8;
                        int c = wn * 32 + nf * 8 + 2 * (l & 3) + (q & 1);
                        float e = (r == c) ? 0.f : ex2(fmaf(acc[mf][nf][q], C1, -C1));
                        rs[mf * 2 + (q >> 1)] += e;
                    }
        } else {  // pos tile
            #pragma unroll
            for (int mf = 0; mf < 4; mf++)
                #pragma unroll
                for (int nf = 0; nf < 4; nf++)
                    #pragma unroll
                    for (int q = 0; q < 4; q++) {
                        float a = acc[mf][nf][q];
                        int r = wm * 64 + mf * 16 + (l >> 2) + (q >> 1) * 8;
                        int c = wn * 32 + nf * 8 + 2 * (l & 3) + (q & 1);
                        float e = ex2(fmaf(a, C1, -C1));
                        if (r == c) {
                            float pv = 2.f * a;
                            g_pos[it * 128 + r] = pv;
                            g_pos[jt * 128 + r] = pv;
                        }
                        rs[mf * 2 + (q >> 1)] += e;
                        cs[nf * 2 + (q & 1)] += e;
                    }
        }

        // rows: reduce over the 4 lanes sharing a row
        #pragma unroll
        for (int u = 0; u < 8; u++) {
            rs[u] += __shfl_xor_sync(0xffffffffu, rs[u], 1);
            rs[u] += __shfl_xor_sync(0xffffffffu, rs[u], 2);
        }
        if ((l & 3) == 0) {
            #pragma unroll
            for (int u = 0; u < 8; u++) {
                int r = wm * 64 + (u >> 1) * 16 + (l >> 2) + 8 * (u & 1);
                Rbuf[wn * 128 + r] = rs[u];
            }
        }
        // cols: reduce over the 8 lanes sharing a column group
        if (!isDiag) {
            #pragma unroll
            for (int u = 0; u < 8; u++) {
                cs[u] += __shfl_xor_sync(0xffffffffu, cs[u], 4);
                cs[u] += __shfl_xor_sync(0xffffffffu, cs[u], 8);
                cs[u] += __shfl_xor_sync(0xffffffffu, cs[u], 16);
            }
            if (l < 4) {
                #pragma unroll
                for (int u = 0; u < 8; u++) {
                    int c = wn * 32 + (u >> 1) * 8 + 2 * l + (u & 1);
                    Cbuf[wm * 128 + c] = cs[u];
                }
            }
        }
        __syncthreads();

        if (tid < 128) {
            float rowtot = (Rbuf[tid] + Rbuf[128 + tid]) + (Rbuf[256 + tid] + Rbuf[384 + tid]);
            g_G[((size_t)it * 128 + jt) * 128 + tid] = rowtot;
            if (!isDiag) {
                float coltot = Cbuf[tid] + Cbuf[128 + tid];
                g_G[((size_t)jt * 128 + it) * 128 + tid] = coltot;
            }
        }
    }
}

__global__ void __launch_bounds__(128) rowreduce_kernel() {
    const int it = blockIdx.x;
    const int r = threadIdx.x;
    const float* Gi = g_G + (size_t)it * 128 * 128 + r;
    float ssum = 0.f;
    #pragma unroll 8
    for (int jt = 0; jt < 128; jt++) ssum += Gi[jt * 128];
    float loss = 2.f + logf(ssum) - g_pos[it * 128 + r];

    __shared__ float red[128];
    red[r] = loss;
    __syncthreads();
    if (r == 0) {
        float acc = 0.f;
        #pragma unroll 8
        for (int i = 0; i < 128; i++) acc += red[i];
        g_partials[it] = acc;
    }
}

__global__ void final_kernel(float* __restrict__ out) {
    if (threadIdx.x == 0) {
        float acc = 0.f;
        for (int i = 0; i < 128; i++) acc += g_partials[i];
        *out = acc / (float)N2;
    }
}

extern "C" void kernel_launch(void* const* d_in, const int* in_sizes, int n_in,
                              void* d_out, int out_size) {
    const float* z = (const float*)d_in[0];
    float* out = (float*)d_out;

    cudaFuncSetAttribute(ntxent_sym_kernel,
                         cudaFuncAttributeMaxDynamicSharedMemorySize, SMEM_BYTES);

    convert_kernel<<<(N2 * DIM / 4) / 256, 256>>>(z);
    ntxent_sym_kernel<<<GRID_MAIN, 256, SMEM_BYTES>>>();
    rowreduce_kernel<<<128, 128>>>();
    final_kernel<<<1, 32>>>(out);
}

// round 6
// speedup vs baseline: 1.0313x; 1.0313x over previous
#include <cuda_runtime.h>
#include <cuda_bf16.h>
#include <cstdint>
#include <math.h>

// NT-Xent loss, symmetric HMMA + software-pipelined epilogue.
// Upper-triangle tile pairs only; previous pair's exp-epilogue is interleaved
// into the current pair's HMMA k-loop (double accumulator banks).

#define N2 16384
#define DIM 128
#define NPAIRS 8256               // 128*129/2
#define GRID_MAIN 152
#define ROWB 272
#define A0_OFF 0
#define A1_OFF 34816
#define B0_OFF 69632
#define B1_OFF 104448
#define RBUF_OFF 139264           // 4*128 floats
#define CBUF_OFF 141312           // 2*128 floats
#define SMEM_BYTES 142336

__device__ __nv_bfloat16 g_zbf[N2 * DIM];
__device__ float g_G[128 * 128 * 128];   // G[it][jt][r]
__device__ float g_pos[N2];
__device__ float g_partials[128];

__device__ __forceinline__ uint32_t smem_u32(const void* p) {
    uint32_t a;
    asm("{ .reg .u64 t; cvta.to.shared.u64 t, %1; cvt.u32.u64 %0, t; }" : "=r"(a) : "l"(p));
    return a;
}
__device__ __forceinline__ void cp16(uint32_t dst, const void* src) {
    asm volatile("cp.async.cg.shared.global [%0], [%1], 16;" :: "r"(dst), "l"(src));
}
__device__ __forceinline__ void ldm_x4(uint32_t (&r)[4], uint32_t addr) {
    asm volatile("ldmatrix.sync.aligned.m8n8.x4.shared.b16 {%0,%1,%2,%3}, [%4];"
                 : "=r"(r[0]), "=r"(r[1]), "=r"(r[2]), "=r"(r[3]) : "r"(addr));
}
__device__ __forceinline__ void mma16816(float (&c)[4], const uint32_t (&a)[4],
                                         uint32_t b0, uint32_t b1) {
    asm volatile("mma.sync.aligned.m16n8k16.row.col.f32.bf16.bf16.f32 "
                 "{%0,%1,%2,%3},{%4,%5,%6,%7},{%8,%9},{%0,%1,%2,%3};"
                 : "+f"(c[0]), "+f"(c[1]), "+f"(c[2]), "+f"(c[3])
                 : "r"(a[0]), "r"(a[1]), "r"(a[2]), "r"(a[3]), "r"(b0), "r"(b1));
}
__device__ __forceinline__ float ex2(float x) {
    float y; asm("ex2.approx.f32 %0, %1;" : "=f"(y) : "f"(x)); return y;
}

#define C1 2.885390081777927f     // 2*log2(e)

__device__ __forceinline__ int Sfun(int t) { return t * 128 - (t * (t - 1)) / 2; }
__device__ __forceinline__ void decode_pair(int p, int& it, int& jt) {
    int t = (int)((257.0 - sqrt((double)(66049 - 8 * p))) * 0.5);
    if (t < 0) t = 0;
    if (t > 127) t = 127;
    while (t < 127 && Sfun(t + 1) <= p) t++;
    while (t > 0 && Sfun(t) > p) t--;
    it = t;
    jt = t + (p - Sfun(t));
}

__global__ void __launch_bounds__(256) convert_kernel(const float* __restrict__ z) {
    int i = blockIdx.x * blockDim.x + threadIdx.x;
    const float4 v = ((const float4*)z)[i];
    __nv_bfloat162 lo = __floats2bfloat162_rn(v.x, v.y);
    __nv_bfloat162 hi = __floats2bfloat162_rn(v.z, v.w);
    uint2 o;
    o.x = *(const uint32_t*)&lo;
    o.y = *(const uint32_t*)&hi;
    ((uint2*)g_zbf)[i] = o;
}

__device__ __forceinline__ void prefetch_tile(uint32_t smbase, const char* gsrc, int tid) {
    #pragma unroll
    for (int i = 0; i < 8; i++) {
        int c = tid + i * 256;
        int r = c >> 4, kc = c & 15;
        cp16(smbase + r * ROWB + kc * 16, gsrc + r * 256 + kc * 16);
    }
}
__device__ __forceinline__ void prefetch_pair(uint32_t s, int buf, int it, int jt, int tid) {
    const char* zbf = (const char*)g_zbf;
    prefetch_tile(s + (buf ? A1_OFF : A0_OFF), zbf + (size_t)it * 32768, tid);
    prefetch_tile(s + (buf ? B1_OFF : B0_OFF), zbf + (size_t)jt * 32768, tid);
}

// MODE 0: plain k-loop. MODE 1: k-loop with interleaved generic epilogue of prev.
template <int MODE>
__device__ __forceinline__ void kloop(float (&cur)[4][4][4], float (&prev)[4][4][4],
                                      float (&rs)[8], float (&cs)[8],
                                      uint32_t A_warp, uint32_t B_warp) {
    #pragma unroll
    for (int mf = 0; mf < 4; mf++)
        #pragma unroll
        for (int nf = 0; nf < 4; nf++)
            #pragma unroll
            for (int q = 0; q < 4; q++) cur[mf][nf][q] = 0.f;

    #pragma unroll
    for (int ks = 0; ks < 8; ks++) {
        uint32_t a[4][4], b[2][4];
        #pragma unroll
        for (int mf = 0; mf < 4; mf++)
            ldm_x4(a[mf], A_warp + mf * (16 * ROWB) + ks * 32);
        #pragma unroll
        for (int nh = 0; nh < 2; nh++)
            ldm_x4(b[nh], B_warp + nh * (16 * ROWB) + ks * 32);
        #pragma unroll
        for (int mf = 0; mf < 4; mf++)
            #pragma unroll
            for (int nf = 0; nf < 4; nf++)
                mma16816(cur[mf][nf], a[mf], b[nf >> 1][(nf & 1) * 2],
                         b[nf >> 1][(nf & 1) * 2 + 1]);
        if (MODE == 1) {
            #pragma unroll
            for (int cc = ks * 2; cc < ks * 2 + 2; cc++) {
                const int mf = cc >> 2, nf = cc & 3;
                #pragma unroll
                for (int q = 0; q < 4; q++) {
                    float e = ex2(fmaf(prev[mf][nf][q], C1, -C1));
                    rs[mf * 2 + (q >> 1)] += e;
                    cs[nf * 2 + (q & 1)] += e;
                }
            }
        }
    }
}

__device__ __forceinline__ void plain_epilogue(float (&prev)[4][4][4],
                                               float (&rs)[8], float (&cs)[8]) {
    #pragma unroll
    for (int mf = 0; mf < 4; mf++)
        #pragma unroll
        for (int nf = 0; nf < 4; nf++)
            #pragma unroll
            for (int q = 0; q < 4; q++) {
                float e = ex2(fmaf(prev[mf][nf][q], C1, -C1));
                rs[mf * 2 + (q >> 1)] += e;
                cs[nf * 2 + (q & 1)] += e;
            }
}

// diag or pos pair: element-indexed epilogue
__device__ __forceinline__ void careful_epilogue(float (&prev)[4][4][4],
                                                 float (&rs)[8], float (&cs)[8],
                                                 bool isDiag, int it, int jt,
                                                 int wm, int wn, int l) {
    #pragma unroll
    for (int mf = 0; mf < 4; mf++)
        #pragma unroll
        for (int nf = 0; nf < 4; nf++)
            #pragma unroll
            for (int q = 0; q < 4; q++) {
                float a = prev[mf][nf][q];
                int r = wm * 64 + mf * 16 + (l >> 2) + (q >> 1) * 8;
                int c = wn * 32 + nf * 8 + 2 * (l & 3) + (q & 1);
                float e = ex2(fmaf(a, C1, -C1));
                if (r == c) {
                    if (isDiag) e = 0.f;
                    else {
                        float pv = 2.f * a;
                        g_pos[it * 128 + r] = pv;
                        g_pos[jt * 128 + r] = pv;
                    }
                }
                rs[mf * 2 + (q >> 1)] += e;
                cs[nf * 2 + (q & 1)] += e;
            }
}

__device__ __forceinline__ void reduce_store(float (&rs)[8], float (&cs)[8],
                                             int it, int jt, bool isDiag,
                                             float* Rbuf, float* Cbuf,
                                             int tid, int wm, int wn, int l) {
    #pragma unroll
    for (int u = 0; u < 8; u++) {
        rs[u] += __shfl_xor_sync(0xffffffffu, rs[u], 1);
        rs[u] += __shfl_xor_sync(0xffffffffu, rs[u], 2);
    }
    if ((l & 3) == 0) {
        #pragma unroll
        for (int u = 0; u < 8; u++) {
            int r = wm * 64 + (u >> 1) * 16 + (l >> 2) + 8 * (u & 1);
            Rbuf[wn * 128 + r] = rs[u];
        }
    }
    if (!isDiag) {
        #pragma unroll
        for (int u = 0; u < 8; u++) {
            cs[u] += __shfl_xor_sync(0xffffffffu, cs[u], 4);
            cs[u] += __shfl_xor_sync(0xffffffffu, cs[u], 8);
            cs[u] += __shfl_xor_sync(0xffffffffu, cs[u], 16);
        }
        if (l < 4) {
            #pragma unroll
            for (int u = 0; u < 8; u++) {
                int c = wn * 32 + (u >> 1) * 8 + 2 * l + (u & 1);
                Cbuf[wm * 128 + c] = cs[u];
            }
        }
    }
    __syncthreads();   // (S2) Rbuf/Cbuf visible
    if (tid < 128) {
        float rowtot = (Rbuf[tid] + Rbuf[128 + tid]) + (Rbuf[256 + tid] + Rbuf[384 + tid]);
        g_G[((size_t)it * 128 + jt) * 128 + tid] = rowtot;
        if (!isDiag) {
            float coltot = Cbuf[tid] + Cbuf[128 + tid];
            g_G[((size_t)jt * 128 + it) * 128 + tid] = coltot;
        }
    }
}

__global__ void __launch_bounds__(256, 1) ntxent_pipe_kernel() {
    extern __shared__ char sm[];
    const uint32_t s = smem_u32(sm);
    float* Rbuf = (float*)(sm + RBUF_OFF);
    float* Cbuf = (float*)(sm + CBUF_OFF);

    const int tid = threadIdx.x;
    const int w = tid >> 5, l = tid & 31;
    const int wm = w >> 2, wn = w & 3;
    const int stride = gridDim.x;

    const uint32_t laneA = (uint32_t)((l & 15) * ROWB + (l >> 4) * 16);
    const uint32_t laneB = (uint32_t)(((l & 7) + ((l >> 4) << 3)) * ROWB + (((l >> 3) & 1) << 4));

    float accA[4][4][4], accB[4][4][4];
    float rs[8], cs[8];

    int prev_it = 0, prev_jt = 0;
    bool prev_diag = false, prev_pos = false, have_prev = false;
    int parity = 0;

    {
        int it0, jt0;
        decode_pair(blockIdx.x, it0, jt0);
        prefetch_pair(s, 0, it0, jt0, tid);
        asm volatile("cp.async.commit_group;" ::: "memory");
    }

    for (int n = blockIdx.x; n < NPAIRS; n += stride) {
        int it, jt;
        decode_pair(n, it, jt);
        int nn = n + stride;
        if (nn < NPAIRS) {
            int it2, jt2;
            decode_pair(nn, it2, jt2);
            prefetch_pair(s, parity ^ 1, it2, jt2, tid);
        }
        asm volatile("cp.async.commit_group;" ::: "memory");
        asm volatile("cp.async.wait_group 1;" ::: "memory");
        __syncthreads();   // (S1) pair n data visible; prior Rbuf reads done

        const uint32_t Abase = s + (parity ? A1_OFF : A0_OFF);
        const uint32_t Bbase = s + (parity ? B1_OFF : B0_OFF);
        const uint32_t A_warp = Abase + (uint32_t)wm * 64 * ROWB + laneA;
        const uint32_t B_warp = Bbase + (uint32_t)wn * 32 * ROWB + laneB;

        #pragma unroll
        for (int u = 0; u < 8; u++) { rs[u] = 0.f; cs[u] = 0.f; }

        const bool special = prev_diag | prev_pos;
        if (have_prev && !special) {
            if (parity == 0) kloop<1>(accA, accB, rs, cs, A_warp, B_warp);
            else             kloop<1>(accB, accA, rs, cs, A_warp, B_warp);
        } else {
            if (parity == 0) kloop<0>(accA, accB, rs, cs, A_warp, B_warp);
            else             kloop<0>(accB, accA, rs, cs, A_warp, B_warp);
            if (have_prev) {
                if (parity == 0) careful_epilogue(accB, rs, cs, prev_diag, prev_it, prev_jt, wm, wn, l);
                else             careful_epilogue(accA, rs, cs, prev_diag, prev_it, prev_jt, wm, wn, l);
            }
        }
        if (have_prev)
            reduce_store(rs, cs, prev_it, prev_jt, prev_diag, Rbuf, Cbuf, tid, wm, wn, l);

        prev_it = it; prev_jt = jt;
        prev_diag = (it == jt);
        prev_pos = (jt - it == 64);
        have_prev = true;
        parity ^= 1;
    }

    // drain last pair (its acc bank is parity^1 after the final flip)
    #pragma unroll
    for (int u = 0; u < 8; u++) { rs[u] = 0.f; cs[u] = 0.f; }
    if (prev_diag | prev_pos) {
        if (parity == 1) careful_epilogue(accA, rs, cs, prev_diag, prev_it, prev_jt, wm, wn, l);
        else             careful_epilogue(accB, rs, cs, prev_diag, prev_it, prev_jt, wm, wn, l);
    } else {
        if (parity == 1) plain_epilogue(accA, rs, cs);
        else             plain_epilogue(accB, rs, cs);
    }
    reduce_store(rs, cs, prev_it, prev_jt, prev_diag, Rbuf, Cbuf, tid, wm, wn, l);
}

__global__ void __launch_bounds__(128) rowreduce_kernel() {
    const int it = blockIdx.x;
    const int r = threadIdx.x;
    const float* Gi = g_G + (size_t)it * 128 * 128 + r;
    float ssum = 0.f;
    #pragma unroll 8
    for (int jt = 0; jt < 128; jt++) ssum += Gi[jt * 128];
    float loss = 2.f + logf(ssum) - g_pos[it * 128 + r];

    __shared__ float red[128];
    red[r] = loss;
    __syncthreads();
    if (r == 0) {
        float acc = 0.f;
        #pragma unroll 8
        for (int i = 0; i < 128; i++) acc += red[i];
        g_partials[it] = acc;
    }
}

__global__ void final_kernel(float* __restrict__ out) {
    if (threadIdx.x == 0) {
        float acc = 0.f;
        for (int i = 0; i < 128; i++) acc += g_partials[i];
        *out = acc / (float)N2;
    }
}

extern "C" void kernel_launch(void* const* d_in, const int* in_sizes, int n_in,
                              void* d_out, int out_size) {
    const float* z = (const float*)d_in[0];
    float* out = (float*)d_out;

    cudaFuncSetAttribute(ntxent_pipe_kernel,
                         cudaFuncAttributeMaxDynamicSharedMemorySize, SMEM_BYTES);

    convert_kernel<<<(N2 * DIM / 4) / 256, 256>>>(z);
    ntxent_pipe_kernel<<<GRID_MAIN, 256, SMEM_BYTES>>>();
    rowreduce_kernel<<<128, 128>>>();
    final_kernel<<<1, 32>>>(out);
}